// round 14
// baseline (speedup 1.0000x reference)
#include <cuda_runtime.h>
#include <cuda_bf16.h>

// Problem constants
#define B_SZ    64
#define S_SZ    512
#define IN_CH   3
#define EXTRA   12
#define AUG_CH  16          // 1 + 3 + 12
#define GROUPS  2
#define SIG_PG  4368        // 16 + 256 + 4096
#define SIG_TOT 8736
#define HIDDEN  256
#define OUT_CH  32
#define SPLIT   3           // chunks per path -> 384 blocks = ONE wave at 3 blk/SM
#define MAXCH   172         // max steps per chunk (ceil(512/3))

// Scratch (device globals — no allocation allowed)
__device__ float g_csig[B_SZ * GROUPS * SPLIT * SIG_PG];  // 6.7 MB chunk sigs
__device__ float g_sig[B_SZ * SIG_TOT];                   // 2.24 MB combined
#define KSPLIT 37
#define CHUNK  237          // 37*237 = 8769 >= 8736 (bounds-checked)
__device__ float g_hacc[B_SZ * HIDDEN];                   // 64 KB: b1 + sig@w1 (atomic)

// ---- packed fp32x2 helpers (sm_103a FFMA2) --------------------------------
__device__ __forceinline__ unsigned long long pack2(float x, float y) {
    unsigned long long r;
    asm("mov.b64 %0, {%1, %2};" : "=l"(r) : "f"(x), "f"(y));
    return r;
}
__device__ __forceinline__ unsigned long long ffma2(unsigned long long a,
                                                    unsigned long long b,
                                                    unsigned long long c) {
    unsigned long long d;
    asm("fma.rn.f32x2 %0, %1, %2, %3;" : "=l"(d) : "l"(a), "l"(b), "l"(c));
    return d;
}
__device__ __forceinline__ void unpack2(unsigned long long v, float& x, float& y) {
    asm("mov.b64 {%0, %1}, %2;" : "=f"(x), "=f"(y) : "l"(v));
}

// ---------------------------------------------------------------------------
// Kernel 1: chunk signatures. blockIdx.x = path*SPLIT + chunk (384 blocks).
// Thread t owns (i,j) = (t>>4, t&15):
//   c2[i,j] scalar, c3[i,j,0..15] as 8 packed f32x2, c1[i] scalar.
// Per step: T2 = c2 + dj*(c1/2 + di/6); c3 += T2*d (8 FFMA2);
//           c2 += dj*(c1 + di/2); c1 += di.
// Post-length increments are pure-time -> collapse to one step of magnitude
// (512-len)/511 at global index n_gen (lands in the last chunk).
// ---------------------------------------------------------------------------
__global__ __launch_bounds__(256, 3)
void sig_chunk_kernel(const float* __restrict__ x,
                      const void*  __restrict__ lengths,
                      const float* __restrict__ aug_w)
{
    __shared__ __align__(16) float d_sh[MAXCH][AUG_CH];  // 10.75 KB
    __shared__ float aw[EXTRA * IN_CH];

    const int blk = blockIdx.x;            // 0..383
    const int p   = blk / SPLIT;           // path 0..127
    const int c   = blk - p * SPLIT;       // chunk 0..2
    const int b   = p >> 1;
    const int g   = p & 1;
    const int tid = threadIdx.x;

    // lengths dtype probe: int64 LE has high word 0 (values in [2,512]).
    const int* Li = (const int*)lengths;
    const int is64 = (Li[1] == 0);
    int len = is64 ? Li[2 * b] : Li[b];
    len = max(2, min(512, len));

    if (tid < EXTRA * IN_CH) aw[tid] = aug_w[g * EXTRA * IN_CH + tid];
    __syncthreads();

    const int n_gen   = len - 1;
    const int n_steps = len;               // + collapsed tail at index n_gen
    const int s0 = (c * n_steps) / SPLIT;
    const int s1 = ((c + 1) * n_steps) / SPLIT;
    const int ns = s1 - s0;                // may be 0
    const float inv = 1.0f / 511.0f;
    const float* xb = x + (size_t)b * S_SZ * IN_CH;

    // Phase 0: build this chunk's increment table.
    for (int s = tid; s < ns; s += 256) {
        const int sg = s0 + s;
        float d0, d1, d2, dt;
        if (sg < n_gen) {
            d0 = xb[(sg + 1) * 3 + 0] - xb[sg * 3 + 0];
            d1 = xb[(sg + 1) * 3 + 1] - xb[sg * 3 + 1];
            d2 = xb[(sg + 1) * 3 + 2] - xb[sg * 3 + 2];
            dt = inv;
        } else {  // sg == n_gen : collapsed pure-time tail
            d0 = d1 = d2 = 0.0f;
            dt = (float)(512 - len) * inv;
        }
        d_sh[s][0] = dt;
        d_sh[s][1] = d0;
        d_sh[s][2] = d1;
        d_sh[s][3] = d2;
        #pragma unroll
        for (int e = 0; e < EXTRA; e++)
            d_sh[s][4 + e] = aw[e * 3 + 0] * d0 + aw[e * 3 + 1] * d1 + aw[e * 3 + 2] * d2;
    }
    __syncthreads();

    const int i = tid >> 4;
    const int j = tid & 15;

    float c1 = 0.0f, c2 = 0.0f;
    unsigned long long c3p[8];
    #pragma unroll
    for (int q = 0; q < 8; q++) c3p[q] = 0ULL;

    for (int s = 0; s < ns; s++) {
        const float* ds = d_sh[s];
        const float di = ds[i];
        const float dj = ds[j];
        const unsigned long long* dp = (const unsigned long long*)ds;  // 8 packed pairs

        const float t2 = fmaf(dj, fmaf(0.5f, c1, di * (1.0f / 6.0f)), c2);
        const unsigned long long t2p = pack2(t2, t2);

        #pragma unroll
        for (int q = 0; q < 8; q++)
            c3p[q] = ffma2(t2p, dp[q], c3p[q]);

        c2 = fmaf(dj, fmaf(0.5f, di, c1), c2);
        c1 += di;
    }

    float* out = g_csig + (size_t)blk * SIG_PG;
    if (j == 0) out[i] = c1;
    out[16 + tid] = c2;
    unsigned long long* o3 = (unsigned long long*)(out + 272 + tid * 16);
    #pragma unroll
    for (int q = 0; q < 8; q++) o3[q] = c3p[q];
}

// ---------------------------------------------------------------------------
// Kernel 1b: fold 3 chunk signatures via Chen's identity, left to right.
//   n1[i]   = a1[i] + b1[i]
//   n2[ij]  = a2[ij] + b2[ij] + a1[i] b1[j]
//   n3[ijk] = a3[ijk] + b3[ijk] + a1[i] b2[jk] + a2[ij] b1[k]
// Also (g==0 blocks) re-initializes g_hacc[b] = b1 for the atomic GEMM.
// ---------------------------------------------------------------------------
__global__ __launch_bounds__(256, 2)
void sig_combine_kernel(const float* __restrict__ bias1)
{
    __shared__ float a1s[16];
    __shared__ float b1s[16];
    __shared__ float b2s[256];

    const int p   = blockIdx.x;        // 0..127
    const int b   = p >> 1;
    const int g   = p & 1;
    const int tid = threadIdx.x;
    const int i   = tid >> 4;
    const int j   = tid & 15;

    // per-replay init of the atomic accumulator (one block per batch row)
    if (g == 0) g_hacc[b * HIDDEN + tid] = bias1[tid];

    const float* buf0 = g_csig + (size_t)(p * SPLIT) * SIG_PG;

    float a2 = buf0[16 + tid];
    float a3[16];
    {
        const float4* b3p = (const float4*)(buf0 + 272 + tid * 16);
        #pragma unroll
        for (int q = 0; q < 4; q++) {
            float4 v = b3p[q];
            a3[q * 4 + 0] = v.x; a3[q * 4 + 1] = v.y;
            a3[q * 4 + 2] = v.z; a3[q * 4 + 3] = v.w;
        }
    }
    if (tid < 16) a1s[tid] = buf0[tid];
    __syncthreads();

    for (int c = 1; c < SPLIT; c++) {
        const float* buf = g_csig + (size_t)(p * SPLIT + c) * SIG_PG;
        if (tid < 16) b1s[tid] = buf[tid];
        b2s[tid] = buf[16 + tid];
        __syncthreads();

        const float a1i = a1s[i];
        const float b1j = b1s[j];
        const float* b2row = &b2s[j * 16];

        // level 3 (uses OLD a1, a2)
        const float4* b3p = (const float4*)(buf + 272 + tid * 16);
        #pragma unroll
        for (int q = 0; q < 4; q++) {
            float4 v = b3p[q];
            a3[q*4+0] += v.x + a1i * b2row[q*4+0] + a2 * b1s[q*4+0];
            a3[q*4+1] += v.y + a1i * b2row[q*4+1] + a2 * b1s[q*4+1];
            a3[q*4+2] += v.z + a1i * b2row[q*4+2] + a2 * b1s[q*4+2];
            a3[q*4+3] += v.w + a1i * b2row[q*4+3] + a2 * b1s[q*4+3];
        }
        // level 2
        a2 += b2s[tid] + a1i * b1j;
        // level 1
        __syncthreads();
        if (tid < 16) a1s[tid] += b1s[tid];
        __syncthreads();
    }

    float* out = g_sig + (size_t)b * SIG_TOT + g * SIG_PG;
    if (j == 0) out[i] = a1s[i];
    out[16 + tid] = a2;
    float4* o3 = (float4*)(out + 272 + tid * 16);
    #pragma unroll
    for (int q = 0; q < 4; q++)
        o3[q] = make_float4(a3[q*4+0], a3[q*4+1], a3[q*4+2], a3[q*4+3]);
}

// ---------------------------------------------------------------------------
// Kernel 2: GEMM1.  h += sig[64,8736] @ w1[8736,256], atomically into g_hacc.
// grid (4 n-tiles of 64, 37 k-splits of 237) = 148 blocks = 1 full wave.
// Per-thread micro-tile 4m x 4n, m-paired FFMA2 (identical to the measured-
// best R9 inner loop); epilogue is 16 RED.F32 per thread instead of STG.
// ---------------------------------------------------------------------------
#define KT 16
__global__ __launch_bounds__(256, 2)
void gemm1_kernel(const float* __restrict__ w1)
{
    __shared__ __align__(16) float As[KT][68];   // [kk][m], padded (272B rows)
    __shared__ __align__(16) float Bs[KT][64];   // [kk][nn]

    const int nt  = blockIdx.x;         // 0..3
    const int ks  = blockIdx.y;         // 0..36
    const int n0b = nt * 64;
    const int k0  = ks * CHUNK;
    const int kend = min(CHUNK, SIG_TOT - k0);
    const int tid = threadIdx.x;

    const int m0 = (tid >> 4) * 4;      // 0,4,..,60
    const int n0 = (tid & 15) * 4;      // 0,4,..,60

    unsigned long long accp[2][4];      // [m-pair][n]
    #pragma unroll
    for (int r = 0; r < 2; r++)
        #pragma unroll
        for (int q = 0; q < 4; q++) accp[r][q] = 0ULL;

    for (int kt = 0; kt < kend; kt += KT) {
        const int klim = min(KT, kend - kt);

        #pragma unroll
        for (int it = 0; it < 4; it++) {           // 64m x 16kk
            int idx = tid + it * 256;
            int kk = idx & 15, m = idx >> 4;
            As[kk][m] = (kk < klim) ? g_sig[(size_t)m * SIG_TOT + k0 + kt + kk] : 0.0f;
        }
        #pragma unroll
        for (int it = 0; it < 4; it++) {           // 16kk x 64nn
            int idx = tid + it * 256;
            int nn = idx & 63, kk = idx >> 6;
            Bs[kk][nn] = (kk < klim) ? w1[(size_t)(k0 + kt + kk) * HIDDEN + n0b + nn] : 0.0f;
        }
        __syncthreads();

        #pragma unroll
        for (int kk = 0; kk < KT; kk++) {
            const ulonglong2 avp = *(const ulonglong2*)&As[kk][m0];  // m-pairs
            const float4 bv = *(const float4*)&Bs[kk][n0];
            const unsigned long long b0 = pack2(bv.x, bv.x);
            const unsigned long long b1 = pack2(bv.y, bv.y);
            const unsigned long long b2 = pack2(bv.z, bv.z);
            const unsigned long long b3 = pack2(bv.w, bv.w);
            accp[0][0] = ffma2(avp.x, b0, accp[0][0]);
            accp[0][1] = ffma2(avp.x, b1, accp[0][1]);
            accp[0][2] = ffma2(avp.x, b2, accp[0][2]);
            accp[0][3] = ffma2(avp.x, b3, accp[0][3]);
            accp[1][0] = ffma2(avp.y, b0, accp[1][0]);
            accp[1][1] = ffma2(avp.y, b1, accp[1][1]);
            accp[1][2] = ffma2(avp.y, b2, accp[1][2]);
            accp[1][3] = ffma2(avp.y, b3, accp[1][3]);
        }
        __syncthreads();
    }

    // epilogue: atomic accumulate into g_hacc (initialized to b1 by combine)
    #pragma unroll
    for (int mp = 0; mp < 2; mp++) {
        float r0[4], r1[4];
        #pragma unroll
        for (int q = 0; q < 4; q++) unpack2(accp[mp][q], r0[q], r1[q]);
        float* row0 = g_hacc + (m0 + 2 * mp + 0) * HIDDEN + n0b + n0;
        float* row1 = g_hacc + (m0 + 2 * mp + 1) * HIDDEN + n0b + n0;
        #pragma unroll
        for (int q = 0; q < 4; q++) {
            atomicAdd(row0 + q, r0[q]);
            atomicAdd(row1 + q, r1[q]);
        }
    }
}

// ---------------------------------------------------------------------------
// Kernel 3: out[m,:] = ReLU(g_hacc[m,:]) @ w2 + b2.  64 blocks; 64KB read.
// ---------------------------------------------------------------------------
__global__ __launch_bounds__(256, 4)
void tail_kernel(const float* __restrict__ w2,
                 const float* __restrict__ b2,
                 float* __restrict__ out)
{
    __shared__ float h[HIDDEN];
    __shared__ float red[8][OUT_CH];

    const int m   = blockIdx.x;
    const int tid = threadIdx.x;

    h[tid] = fmaxf(g_hacc[m * HIDDEN + tid], 0.0f);
    __syncthreads();

    const int oc = tid & 31;
    const int kc = tid >> 5;           // 8 chunks of 32
    float a = 0.0f;
    #pragma unroll
    for (int kk = 0; kk < 32; kk++) {
        int k = kc * 32 + kk;
        a = fmaf(h[k], w2[k * OUT_CH + oc], a);
    }
    red[kc][oc] = a;
    __syncthreads();

    if (tid < OUT_CH) {
        float r = b2[tid];
        #pragma unroll
        for (int c = 0; c < 8; c++) r += red[c][tid];
        out[m * OUT_CH + tid] = r;
    }
}

// ---------------------------------------------------------------------------
extern "C" void kernel_launch(void* const* d_in, const int* in_sizes, int n_in,
                              void* d_out, int out_size)
{
    const float* x       = (const float*)d_in[0];
    const void*  lengths = d_in[1];
    const float* aug_w   = (const float*)d_in[2];
    // d_in[3] = aug_b : unused (signature is translation invariant)
    const float* w1      = (const float*)d_in[4];
    const float* b1      = (const float*)d_in[5];
    const float* w2      = (const float*)d_in[6];
    const float* b2      = (const float*)d_in[7];
    float* out           = (float*)d_out;

    sig_chunk_kernel<<<B_SZ * GROUPS * SPLIT, 256>>>(x, lengths, aug_w);
    sig_combine_kernel<<<B_SZ * GROUPS, 256>>>(b1);
    gemm1_kernel<<<dim3(4, KSPLIT), 256>>>(w1);
    tail_kernel<<<B_SZ, 256>>>(w2, b2, out);
}